// round 13
// baseline (speedup 1.0000x reference)
#include <cuda_runtime.h>
#include <cuda_fp16.h>
#include <math.h>

#define N_NODES 50000
#define NNZ     800000
#define N_ADJ   6
#define K_IN    256
#define N_HID   128
#define LN_EPS  1e-5f
#define CAP     64          // bucket capacity (Poisson(16): P(>40)~2e-7)

// ---- scratch (no allocation allowed -> __device__ globals) ----
__device__ __half   g_h [N_NODES * N_HID];
__device__ __half   g_s1[N_NODES * N_HID];
__device__ __half   g_s2[N_NODES * N_HID];
__device__ int      g_cnt [N_ADJ * N_NODES];
__device__ unsigned g_pedge[(size_t)N_ADJ * N_NODES * CAP]; // {col lo16, half(val) hi16}

// ---- helpers ----
__device__ __forceinline__ float hbits_to_f(unsigned hi16)
{
    return __half2float(__ushort_as_half((unsigned short)hi16));
}

__device__ __forceinline__ unsigned f2tf32(float f)
{
    unsigned r;
    asm volatile("cvt.rna.tf32.f32 %0, %1;" : "=r"(r) : "f"(f));
    return r;
}

// acc: 4 packed f32x2 pairs (8 floats). One FFMA2 per half2 of x.
__device__ __forceinline__ void fma_h8x2(
    unsigned long long* acc, unsigned long long vv, uint4 u)
{
    unsigned p[4] = {u.x, u.y, u.z, u.w};
#pragma unroll
    for (int q = 0; q < 4; q++) {
        __half2 hh = *reinterpret_cast<__half2*>(&p[q]);
        float2 f = __half22float2(hh);
        unsigned long long xf;
        asm("mov.b64 %0, {%1, %2};" : "=l"(xf) : "f"(f.x), "f"(f.y));
        asm("fma.rn.f32x2 %0, %1, %2, %0;" : "+l"(acc[q]) : "l"(xf), "l"(vv));
    }
}

__device__ __forceinline__ unsigned long long pack2(float v)
{
    unsigned long long r;
    asm("mov.b64 %0, {%1, %1};" : "=l"(r) : "f"(v));
    return r;
}

__device__ __forceinline__ void unpack_acc(const unsigned long long* a, float* f)
{
#pragma unroll
    for (int q = 0; q < 4; q++)
        asm("mov.b64 {%0, %1}, %2;" : "=f"(f[2 * q]), "=f"(f[2 * q + 1]) : "l"(a[q]));
}

// inline "is adjacency a used?" check
__device__ __forceinline__ bool adj_used(
    int a, const int* __restrict__ seq, const int* __restrict__ res)
{
    return a == seq[0] || a == seq[1] || a == seq[2] ||
           a == res[0] || a == res[1] || a == res[2];
}

// ============================================================================
// tf32 tensor-core GEMM: h = x @ W + b   (fp32 in, tf32 mma, fp32 acc, fp16 out)
// ============================================================================
#define GM 64
#define KC 32

__global__ __launch_bounds__(256) void gemm_tf32_kernel(
    const float* __restrict__ x, const float* __restrict__ W,
    const float* __restrict__ b, __half* __restrict__ out)
{
    __shared__ __align__(16) float xs[GM][KC + 1];
    __shared__ __align__(16) float ws[KC][N_HID + 2];

    const int tid  = threadIdx.x;
    const int lane = tid & 31;
    const int wid  = tid >> 5;
    const int wm   = wid & 3;
    const int wn   = wid >> 2;
    const int row0 = blockIdx.x * GM;
    const int g    = lane >> 2;
    const int t4   = lane & 3;

    float c[8][4];
#pragma unroll
    for (int j = 0; j < 8; j++)
#pragma unroll
        for (int i = 0; i < 4; i++) c[j][i] = 0.f;

    for (int kc = 0; kc < K_IN; kc += KC) {
#pragma unroll
        for (int t = 0; t < 2; t++) {
            int idx = tid + t * 256;
            int r   = idx >> 3;
            int kq  = idx & 7;
            float4 v = make_float4(0.f, 0.f, 0.f, 0.f);
            int grow = row0 + r;
            if (grow < N_NODES)
                v = *(const float4*)(x + (size_t)grow * K_IN + kc + kq * 4);
            xs[r][kq * 4 + 0] = v.x;
            xs[r][kq * 4 + 1] = v.y;
            xs[r][kq * 4 + 2] = v.z;
            xs[r][kq * 4 + 3] = v.w;
        }
#pragma unroll
        for (int t = 0; t < 4; t++) {
            int idx = tid + t * 256;
            int kk  = idx >> 5;
            int c4  = idx & 31;
            float4 v = *(const float4*)(W + (size_t)(kc + kk) * N_HID + c4 * 4);
            ws[kk][c4 * 4 + 0] = v.x;
            ws[kk][c4 * 4 + 1] = v.y;
            ws[kk][c4 * 4 + 2] = v.z;
            ws[kk][c4 * 4 + 3] = v.w;
        }
        __syncthreads();

#pragma unroll
        for (int k0 = 0; k0 < KC; k0 += 8) {
            unsigned a0 = f2tf32(xs[wm * 16 + g    ][k0 + t4    ]);
            unsigned a1 = f2tf32(xs[wm * 16 + g + 8][k0 + t4    ]);
            unsigned a2 = f2tf32(xs[wm * 16 + g    ][k0 + t4 + 4]);
            unsigned a3 = f2tf32(xs[wm * 16 + g + 8][k0 + t4 + 4]);
#pragma unroll
            for (int j = 0; j < 8; j++) {
                int n0 = wn * 64 + j * 8;
                unsigned b0 = f2tf32(ws[k0 + t4    ][n0 + g]);
                unsigned b1 = f2tf32(ws[k0 + t4 + 4][n0 + g]);
                asm volatile(
                    "mma.sync.aligned.m16n8k8.row.col.f32.tf32.tf32.f32 "
                    "{%0,%1,%2,%3}, {%4,%5,%6,%7}, {%8,%9}, {%0,%1,%2,%3};\n"
                    : "+f"(c[j][0]), "+f"(c[j][1]), "+f"(c[j][2]), "+f"(c[j][3])
                    : "r"(a0), "r"(a1), "r"(a2), "r"(a3), "r"(b0), "r"(b1));
            }
        }
        __syncthreads();
    }

#pragma unroll
    for (int j = 0; j < 8; j++) {
        int col = wn * 64 + j * 8 + 2 * t4;
        float2 bv = *(const float2*)(b + col);
        int r0 = row0 + wm * 16 + g;
        if (r0 < N_NODES)
            *(__half2*)(out + (size_t)r0 * N_HID + col) =
                __floats2half2_rn(c[j][0] + bv.x, c[j][1] + bv.y);
        int r1 = r0 + 8;
        if (r1 < N_NODES)
            *(__half2*)(out + (size_t)r1 * N_HID + col) =
                __floats2half2_rn(c[j][2] + bv.x, c[j][3] + bv.y);
    }
}

// ============================================================================
// bucket scatter: 4B packed records, atomic cursor (counters pre-zeroed by memset)
// ============================================================================
__global__ __launch_bounds__(256) void scatter_kernel(
    const int* __restrict__ rows, const int* __restrict__ cols,
    const float* __restrict__ vals,
    const int* __restrict__ seq, const int* __restrict__ res)
{
    int a = blockIdx.y;
    if (!adj_used(a, seq, res)) return;
    int e = blockIdx.x * 256 + threadIdx.x;
    if (e >= NNZ) return;
    size_t idx = (size_t)a * NNZ + e;
    int r = rows[idx];
    int p = atomicAdd(&g_cnt[a * N_NODES + r], 1);
    if (p < CAP) {
        unsigned hv = __half_as_ushort(__float2half_rn(vals[idx]));
        unsigned pk = (unsigned)cols[idx] | (hv << 16);   // col < 65536
        g_pedge[((size_t)a * N_NODES + r) * CAP + p] = pk;
    }
}

// ============================================================================
// Gather SpMM: HALF-WARP per row; sub-lane s owns cols [8s,8s+8) (uint4 fp16).
// Segment-masked shuffles; padded slots hold packed 0 -> fma no-op.
// Accumulators: 4 packed f32x2 pairs, FFMA2 inner loop.
// ============================================================================
__device__ __forceinline__ void accum_row8(
    unsigned long long* acc, int a, int row, const uint4* __restrict__ src,
    int sub, unsigned seg)
{
    int n = g_cnt[a * N_NODES + row];
    n = n < CAP ? n : CAP;
    const unsigned* ep = g_pedge + ((size_t)a * N_NODES + row) * CAP;

    unsigned m[4];
#pragma unroll
    for (int j = 0; j < 4; j++)
        m[j] = (sub + 16 * j < n) ? __ldg(ep + sub + 16 * j) : 0u;

    int n8 = (n + 7) & ~7;
    for (int e = 0; e < n8; e += 8) {
        unsigned mm = (e & 16) ? ((e & 32) ? m[3] : m[1])
                               : ((e & 32) ? m[2] : m[0]);
        int sl = e & 15;
        unsigned w[8];
#pragma unroll
        for (int j = 0; j < 8; j++)
            w[j] = __shfl_sync(seg, mm, sl + j, 16);

        uint4 xv[8];
#pragma unroll
        for (int j = 0; j < 8; j++)
            xv[j] = __ldg(src + (size_t)(w[j] & 0xFFFFu) * 16 + sub);
#pragma unroll
        for (int j = 0; j < 8; j++)
            fma_h8x2(acc, pack2(hbits_to_f(w[j] >> 16)), xv[j]);
    }
}

__device__ __forceinline__ uint4 f8_to_h8(const float* a)
{
    __half2 h0 = __floats2half2_rn(a[0], a[1]);
    __half2 h1 = __floats2half2_rn(a[2], a[3]);
    __half2 h2 = __floats2half2_rn(a[4], a[5]);
    __half2 h3 = __floats2half2_rn(a[6], a[7]);
    uint4 u;
    u.x = *reinterpret_cast<unsigned*>(&h0);
    u.y = *reinterpret_cast<unsigned*>(&h1);
    u.z = *reinterpret_cast<unsigned*>(&h2);
    u.w = *reinterpret_cast<unsigned*>(&h3);
    return u;
}

// s1 = A[seq0] @ h        (16 rows per 256-thread block; 50000/16 = 3125 exact)
__global__ __launch_bounds__(256) void spmm_k1(const int* __restrict__ idx_seq)
{
    int lane = threadIdx.x & 31;
    int sub  = lane & 15;
    unsigned seg = 0xFFFFu << ((lane >> 4) * 16);
    int row  = blockIdx.x * 16 + (threadIdx.x >> 5) * 2 + (lane >> 4);
    unsigned long long acc[4] = {0ull, 0ull, 0ull, 0ull};
    accum_row8(acc, idx_seq[0], row, (const uint4*)g_h, sub, seg);
    float f[8];
    unpack_acc(acc, f);
    ((uint4*)g_s1)[(size_t)row * 16 + sub] = f8_to_h8(f);
}

// s2 = A[seq1] @ s1 + A[res0] @ h
__global__ __launch_bounds__(256) void spmm_k2(
    const int* __restrict__ idx_seq, const int* __restrict__ idx_res)
{
    int lane = threadIdx.x & 31;
    int sub  = lane & 15;
    unsigned seg = 0xFFFFu << ((lane >> 4) * 16);
    int row  = blockIdx.x * 16 + (threadIdx.x >> 5) * 2 + (lane >> 4);
    unsigned long long acc[4] = {0ull, 0ull, 0ull, 0ull};
    accum_row8(acc, idx_seq[1], row, (const uint4*)g_s1, sub, seg);
    accum_row8(acc, idx_res[0], row, (const uint4*)g_h,  sub, seg);
    float f[8];
    unpack_acc(acc, f);
    ((uint4*)g_s2)[(size_t)row * 16 + sub] = f8_to_h8(f);
}

__device__ __forceinline__ float gelu_exact(float x)
{
    return 0.5f * x * (1.f + erff(x * 0.70710678118654752f));
}

// out = LN+GELU( A[seq2] @ s2 + A[res1] @ h + A[res2] @ s1 )   (fp32 out)
__global__ __launch_bounds__(256) void spmm_k3_ln(
    const int* __restrict__ idx_seq, const int* __restrict__ idx_res,
    const float* __restrict__ gamma, const float* __restrict__ beta,
    float* __restrict__ out)
{
    int lane = threadIdx.x & 31;
    int sub  = lane & 15;
    unsigned seg = 0xFFFFu << ((lane >> 4) * 16);
    int row  = blockIdx.x * 16 + (threadIdx.x >> 5) * 2 + (lane >> 4);
    unsigned long long acc[4] = {0ull, 0ull, 0ull, 0ull};
    accum_row8(acc, idx_seq[2], row, (const uint4*)g_s2, sub, seg);
    accum_row8(acc, idx_res[1], row, (const uint4*)g_h,  sub, seg);
    accum_row8(acc, idx_res[2], row, (const uint4*)g_s1, sub, seg);

    float af[8];
    unpack_acc(acc, af);

    float s = 0.f, sq = 0.f;
#pragma unroll
    for (int j = 0; j < 8; j++) { s += af[j]; sq += af[j] * af[j]; }
#pragma unroll
    for (int o = 8; o > 0; o >>= 1) {
        s  += __shfl_xor_sync(seg, s,  o, 16);
        sq += __shfl_xor_sync(seg, sq, o, 16);
    }
    float mu   = s * (1.f / 128.f);
    float var  = sq * (1.f / 128.f) - mu * mu;
    float rstd = rsqrtf(var + LN_EPS);

    float4 g0  = *(const float4*)(gamma + sub * 8);
    float4 g1  = *(const float4*)(gamma + sub * 8 + 4);
    float4 b0  = *(const float4*)(beta  + sub * 8);
    float4 b1  = *(const float4*)(beta  + sub * 8 + 4);
    float gg[8] = {g0.x, g0.y, g0.z, g0.w, g1.x, g1.y, g1.z, g1.w};
    float bb[8] = {b0.x, b0.y, b0.z, b0.w, b1.x, b1.y, b1.z, b1.w};

    float o8[8];
#pragma unroll
    for (int j = 0; j < 8; j++)
        o8[j] = gelu_exact((af[j] - mu) * rstd * gg[j] + bb[j]);

    float4* op = (float4*)(out + (size_t)row * N_HID + sub * 8);
    op[0] = make_float4(o8[0], o8[1], o8[2], o8[3]);
    op[1] = make_float4(o8[4], o8[5], o8[6], o8[7]);
}

// ============================================================================
// launch — forked capture: tf32 GEMM overlaps memset+scatter build
// ============================================================================
extern "C" void kernel_launch(void* const* d_in, const int* in_sizes, int n_in,
                              void* d_out, int out_size)
{
    const float* x         = (const float*)d_in[0];
    const int*   adj_rows  = (const int*)  d_in[1];
    const int*   adj_cols  = (const int*)  d_in[2];
    const float* adj_vals  = (const float*)d_in[3];
    const int*   idxes_seq = (const int*)  d_in[4];
    const int*   idxes_res = (const int*)  d_in[5];
    const float* W         = (const float*)d_in[6];
    const float* b         = (const float*)d_in[7];
    const float* gamma     = (const float*)d_in[8];
    const float* beta      = (const float*)d_in[9];
    float*       out       = (float*)d_out;

    __half* h;
    int*    cnt;
    cudaGetSymbolAddress((void**)&h,   g_h);
    cudaGetSymbolAddress((void**)&cnt, g_cnt);

    const int  gemm_blocks = (N_NODES + GM - 1) / GM;          // 782
    const dim3 edge_grid((NNZ + 255) / 256, N_ADJ);
    const int  row_blocks  = N_NODES / 16;                     // 3125 exact

    cudaStream_t s2;
    cudaStreamCreateWithFlags(&s2, cudaStreamNonBlocking);
    cudaEvent_t evFork, evGemm;
    cudaEventCreateWithFlags(&evFork, cudaEventDisableTiming);
    cudaEventCreateWithFlags(&evGemm, cudaEventDisableTiming);

    // fork: GEMM on side stream (compute-bound, hides under L2-bound build)
    cudaEventRecord(evFork, 0);
    cudaStreamWaitEvent(s2, evFork, 0);
    gemm_tf32_kernel<<<gemm_blocks, 256, 0, s2>>>(x, W, b, h);
    cudaEventRecord(evGemm, s2);

    // origin stream: zero counters via memset node, then scatter
    cudaMemsetAsync(cnt, 0, (size_t)N_ADJ * N_NODES * sizeof(int), 0);
    scatter_kernel<<<edge_grid, 256>>>(adj_rows, adj_cols, adj_vals,
                                       idxes_seq, idxes_res);

    // join: SpMMs need both h and the buckets
    cudaStreamWaitEvent(0, evGemm, 0);
    spmm_k1<<<row_blocks, 256>>>(idxes_seq);
    spmm_k2<<<row_blocks, 256>>>(idxes_seq, idxes_res);
    spmm_k3_ln<<<row_blocks, 256>>>(idxes_seq, idxes_res, gamma, beta, out);
}

// round 14
// speedup vs baseline: 1.0116x; 1.0116x over previous
#include <cuda_runtime.h>
#include <cuda_fp16.h>
#include <math.h>

#define N_NODES 50000
#define NNZ     800000
#define N_ADJ   6
#define K_IN    256
#define N_HID   128
#define LN_EPS  1e-5f
#define CAP     64          // bucket capacity (Poisson(16): P(>40)~2e-7)

// ---- scratch (no allocation allowed -> __device__ globals) ----
__device__ __half   g_h [N_NODES * N_HID];
__device__ __half   g_s1[N_NODES * N_HID];
__device__ __half   g_s2[N_NODES * N_HID];
__device__ __half   g_t [N_NODES * N_HID];    // k3a partial (res1@h + res2@s1)
__device__ int      g_cnt [N_ADJ * N_NODES];
__device__ unsigned g_pedge[(size_t)N_ADJ * N_NODES * CAP]; // {col lo16, half(val) hi16}

// ---- helpers ----
__device__ __forceinline__ uint2 f4_to_h4(float4 a)
{
    __half2 lo = __floats2half2_rn(a.x, a.y);
    __half2 hi = __floats2half2_rn(a.z, a.w);
    uint2 u;
    u.x = *reinterpret_cast<unsigned int*>(&lo);
    u.y = *reinterpret_cast<unsigned int*>(&hi);
    return u;
}

// acc[8] += v * (8 halfs packed in uint4)   -- plain FFMA path (R9, measured best)
__device__ __forceinline__ void fma_h8(float* acc, float v, uint4 u)
{
    unsigned p[4] = {u.x, u.y, u.z, u.w};
#pragma unroll
    for (int q = 0; q < 4; q++) {
        __half2 hh = *reinterpret_cast<__half2*>(&p[q]);
        float2 f = __half22float2(hh);
        acc[q * 2 + 0] = fmaf(v, f.x, acc[q * 2 + 0]);
        acc[q * 2 + 1] = fmaf(v, f.y, acc[q * 2 + 1]);
    }
}

__device__ __forceinline__ float hbits_to_f(unsigned hi16)
{
    return __half2float(__ushort_as_half((unsigned short)hi16));
}

// inline "is adjacency a used?" check
__device__ __forceinline__ bool adj_used(
    int a, const int* __restrict__ seq, const int* __restrict__ res)
{
    return a == seq[0] || a == seq[1] || a == seq[2] ||
           a == res[0] || a == res[1] || a == res[2];
}

// ============================================================================
// GEMM (R9 fp32 version): h = x @ W + b   (fp32 math, fp16 store)
// ============================================================================
#define GR 64
#define KC 32

__global__ __launch_bounds__(256) void gemm_kernel(
    const float* __restrict__ x, const float* __restrict__ W,
    const float* __restrict__ b, __half* __restrict__ out)
{
    __shared__ __align__(16) float xs[KC][GR];
    __shared__ __align__(16) float ws[KC][N_HID];

    const int tid = threadIdx.x;
    const int tx = tid & 31;
    const int ty = tid >> 5;
    const int row0 = blockIdx.x * GR;

    float acc[8][4];
#pragma unroll
    for (int i = 0; i < 8; i++)
#pragma unroll
        for (int j = 0; j < 4; j++) acc[i][j] = 0.f;

    for (int kc = 0; kc < K_IN; kc += KC) {
#pragma unroll
        for (int t = 0; t < 2; t++) {
            int idx = tid + t * 256;
            int r   = idx >> 3;
            int kq  = idx & 7;
            float4 v = make_float4(0.f, 0.f, 0.f, 0.f);
            int grow = row0 + r;
            if (grow < N_NODES)
                v = *(const float4*)(x + (size_t)grow * K_IN + kc + kq * 4);
            xs[kq * 4 + 0][r] = v.x;
            xs[kq * 4 + 1][r] = v.y;
            xs[kq * 4 + 2][r] = v.z;
            xs[kq * 4 + 3][r] = v.w;
        }
#pragma unroll
        for (int t = 0; t < 4; t++) {
            int idx = tid + t * 256;
            int kk  = idx >> 5;
            int c4  = idx & 31;
            *(float4*)&ws[kk][c4 * 4] =
                *(const float4*)(W + (size_t)(kc + kk) * N_HID + c4 * 4);
        }
        __syncthreads();

#pragma unroll
        for (int k = 0; k < KC; k++) {
            float4 xa = *(const float4*)&xs[k][ty * 8];
            float4 xb = *(const float4*)&xs[k][ty * 8 + 4];
            float4 wv = *(const float4*)&ws[k][tx * 4];
            float xr[8] = {xa.x, xa.y, xa.z, xa.w, xb.x, xb.y, xb.z, xb.w};
            float wr[4] = {wv.x, wv.y, wv.z, wv.w};
#pragma unroll
            for (int i = 0; i < 8; i++)
#pragma unroll
                for (int j = 0; j < 4; j++) acc[i][j] += xr[i] * wr[j];
        }
        __syncthreads();
    }

    float4 bv = *(const float4*)(b + tx * 4);
#pragma unroll
    for (int i = 0; i < 8; i++) {
        int grow = row0 + ty * 8 + i;
        if (grow < N_NODES) {
            float4 o;
            o.x = acc[i][0] + bv.x;
            o.y = acc[i][1] + bv.y;
            o.z = acc[i][2] + bv.z;
            o.w = acc[i][3] + bv.w;
            ((uint2*)out)[(size_t)grow * 32 + tx] = f4_to_h4(o);
        }
    }
}

// ============================================================================
// bucket scatter: 4B packed records, atomic cursor (counters zeroed by memset)
// ============================================================================
__global__ __launch_bounds__(256) void scatter_kernel(
    const int* __restrict__ rows, const int* __restrict__ cols,
    const float* __restrict__ vals,
    const int* __restrict__ seq, const int* __restrict__ res)
{
    int a = blockIdx.y;
    if (!adj_used(a, seq, res)) return;
    int e = blockIdx.x * 256 + threadIdx.x;
    if (e >= NNZ) return;
    size_t idx = (size_t)a * NNZ + e;
    int r = rows[idx];
    int p = atomicAdd(&g_cnt[a * N_NODES + r], 1);
    if (p < CAP) {
        unsigned hv = __half_as_ushort(__float2half_rn(vals[idx]));
        unsigned pk = (unsigned)cols[idx] | (hv << 16);   // col < 65536
        g_pedge[((size_t)a * N_NODES + r) * CAP + p] = pk;
    }
}

// ============================================================================
// Gather SpMM (R9 form): HALF-WARP per row; sub-lane s owns cols [8s,8s+8).
// Segment-masked shuffles; padded slots hold packed 0 -> fma no-op.
// ============================================================================
__device__ __forceinline__ void accum_row8(
    float* acc, int a, int row, const uint4* __restrict__ src,
    int sub, unsigned seg)
{
    int n = g_cnt[a * N_NODES + row];
    n = n < CAP ? n : CAP;
    const unsigned* ep = g_pedge + ((size_t)a * N_NODES + row) * CAP;

    unsigned m[4];
#pragma unroll
    for (int j = 0; j < 4; j++)
        m[j] = (sub + 16 * j < n) ? __ldg(ep + sub + 16 * j) : 0u;

    int n8 = (n + 7) & ~7;
    for (int e = 0; e < n8; e += 8) {
        unsigned mm = (e & 16) ? ((e & 32) ? m[3] : m[1])
                               : ((e & 32) ? m[2] : m[0]);
        int sl = e & 15;
        unsigned w[8];
#pragma unroll
        for (int j = 0; j < 8; j++)
            w[j] = __shfl_sync(seg, mm, sl + j, 16);

        uint4 xv[8];
#pragma unroll
        for (int j = 0; j < 8; j++)
            xv[j] = __ldg(src + (size_t)(w[j] & 0xFFFFu) * 16 + sub);
#pragma unroll
        for (int j = 0; j < 8; j++)
            fma_h8(acc, hbits_to_f(w[j] >> 16), xv[j]);
    }
}

__device__ __forceinline__ uint4 f8_to_h8(const float* a)
{
    __half2 h0 = __floats2half2_rn(a[0], a[1]);
    __half2 h1 = __floats2half2_rn(a[2], a[3]);
    __half2 h2 = __floats2half2_rn(a[4], a[5]);
    __half2 h3 = __floats2half2_rn(a[6], a[7]);
    uint4 u;
    u.x = *reinterpret_cast<unsigned*>(&h0);
    u.y = *reinterpret_cast<unsigned*>(&h1);
    u.z = *reinterpret_cast<unsigned*>(&h2);
    u.w = *reinterpret_cast<unsigned*>(&h3);
    return u;
}

// s1 = A[seq0] @ h        (16 rows per 256-thread block; 50000/16 = 3125 exact)
__global__ __launch_bounds__(256) void spmm_k1(const int* __restrict__ idx_seq)
{
    int lane = threadIdx.x & 31;
    int sub  = lane & 15;
    unsigned seg = 0xFFFFu << ((lane >> 4) * 16);
    int row  = blockIdx.x * 16 + (threadIdx.x >> 5) * 2 + (lane >> 4);
    float acc[8] = {0.f, 0.f, 0.f, 0.f, 0.f, 0.f, 0.f, 0.f};
    accum_row8(acc, idx_seq[0], row, (const uint4*)g_h, sub, seg);
    ((uint4*)g_s1)[(size_t)row * 16 + sub] = f8_to_h8(acc);
}

// s2 = A[seq1] @ s1 + A[res0] @ h
__global__ __launch_bounds__(256) void spmm_k2(
    const int* __restrict__ idx_seq, const int* __restrict__ idx_res)
{
    int lane = threadIdx.x & 31;
    int sub  = lane & 15;
    unsigned seg = 0xFFFFu << ((lane >> 4) * 16);
    int row  = blockIdx.x * 16 + (threadIdx.x >> 5) * 2 + (lane >> 4);
    float acc[8] = {0.f, 0.f, 0.f, 0.f, 0.f, 0.f, 0.f, 0.f};
    accum_row8(acc, idx_seq[1], row, (const uint4*)g_s1, sub, seg);
    accum_row8(acc, idx_res[0], row, (const uint4*)g_h,  sub, seg);
    ((uint4*)g_s2)[(size_t)row * 16 + sub] = f8_to_h8(acc);
}

// t = A[res1] @ h + A[res2] @ s1    (k3 split, part A -- L2-capacity relief)
__global__ __launch_bounds__(256) void spmm_k3a(const int* __restrict__ idx_res)
{
    int lane = threadIdx.x & 31;
    int sub  = lane & 15;
    unsigned seg = 0xFFFFu << ((lane >> 4) * 16);
    int row  = blockIdx.x * 16 + (threadIdx.x >> 5) * 2 + (lane >> 4);
    float acc[8] = {0.f, 0.f, 0.f, 0.f, 0.f, 0.f, 0.f, 0.f};
    accum_row8(acc, idx_res[1], row, (const uint4*)g_h,  sub, seg);
    accum_row8(acc, idx_res[2], row, (const uint4*)g_s1, sub, seg);
    ((uint4*)g_t)[(size_t)row * 16 + sub] = f8_to_h8(acc);
}

__device__ __forceinline__ float gelu_exact(float x)
{
    return 0.5f * x * (1.f + erff(x * 0.70710678118654752f));
}

// out = LN+GELU( A[seq2] @ s2 + t )    (k3 split, part B; fp32 out)
__global__ __launch_bounds__(256) void spmm_k3b_ln(
    const int* __restrict__ idx_seq,
    const float* __restrict__ gamma, const float* __restrict__ beta,
    float* __restrict__ out)
{
    int lane = threadIdx.x & 31;
    int sub  = lane & 15;
    unsigned seg = 0xFFFFu << ((lane >> 4) * 16);
    int row  = blockIdx.x * 16 + (threadIdx.x >> 5) * 2 + (lane >> 4);
    float acc[8] = {0.f, 0.f, 0.f, 0.f, 0.f, 0.f, 0.f, 0.f};
    accum_row8(acc, idx_seq[2], row, (const uint4*)g_s2, sub, seg);

    // add the k3a partial
    {
        uint4 t = ((const uint4*)g_t)[(size_t)row * 16 + sub];
        unsigned tp[4] = {t.x, t.y, t.z, t.w};
#pragma unroll
        for (int q = 0; q < 4; q++) {
            float2 f = __half22float2(*reinterpret_cast<__half2*>(&tp[q]));
            acc[q * 2 + 0] += f.x;
            acc[q * 2 + 1] += f.y;
        }
    }

    float s = 0.f, sq = 0.f;
#pragma unroll
    for (int j = 0; j < 8; j++) { s += acc[j]; sq += acc[j] * acc[j]; }
#pragma unroll
    for (int o = 8; o > 0; o >>= 1) {
        s  += __shfl_xor_sync(seg, s,  o, 16);
        sq += __shfl_xor_sync(seg, sq, o, 16);
    }
    float mu   = s * (1.f / 128.f);
    float var  = sq * (1.f / 128.f) - mu * mu;
    float rstd = rsqrtf(var + LN_EPS);

    float4 g0  = *(const float4*)(gamma + sub * 8);
    float4 g1  = *(const float4*)(gamma + sub * 8 + 4);
    float4 b0  = *(const float4*)(beta  + sub * 8);
    float4 b1  = *(const float4*)(beta  + sub * 8 + 4);
    float gg[8] = {g0.x, g0.y, g0.z, g0.w, g1.x, g1.y, g1.z, g1.w};
    float bb[8] = {b0.x, b0.y, b0.z, b0.w, b1.x, b1.y, b1.z, b1.w};

    float o8[8];
#pragma unroll
    for (int j = 0; j < 8; j++)
        o8[j] = gelu_exact((acc[j] - mu) * rstd * gg[j] + bb[j]);

    float4* op = (float4*)(out + (size_t)row * N_HID + sub * 8);
    op[0] = make_float4(o8[0], o8[1], o8[2], o8[3]);
    op[1] = make_float4(o8[4], o8[5], o8[6], o8[7]);
}

// ============================================================================
// launch — forked capture: fp32 GEMM (compute-bound) overlaps memset+scatter
// ============================================================================
extern "C" void kernel_launch(void* const* d_in, const int* in_sizes, int n_in,
                              void* d_out, int out_size)
{
    const float* x         = (const float*)d_in[0];
    const int*   adj_rows  = (const int*)  d_in[1];
    const int*   adj_cols  = (const int*)  d_in[2];
    const float* adj_vals  = (const float*)d_in[3];
    const int*   idxes_seq = (const int*)  d_in[4];
    const int*   idxes_res = (const int*)  d_in[5];
    const float* W         = (const float*)d_in[6];
    const float* b         = (const float*)d_in[7];
    const float* gamma     = (const float*)d_in[8];
    const float* beta      = (const float*)d_in[9];
    float*       out       = (float*)d_out;

    __half* h;
    int*    cnt;
    cudaGetSymbolAddress((void**)&h,   g_h);
    cudaGetSymbolAddress((void**)&cnt, g_cnt);

    const int  gemm_blocks = (N_NODES + GR - 1) / GR;          // 782
    const dim3 edge_grid((NNZ + 255) / 256, N_ADJ);
    const int  row_blocks  = N_NODES / 16;                     // 3125 exact

    cudaStream_t s2;
    cudaStreamCreateWithFlags(&s2, cudaStreamNonBlocking);
    cudaEvent_t evFork, evGemm;
    cudaEventCreateWithFlags(&evFork, cudaEventDisableTiming);
    cudaEventCreateWithFlags(&evGemm, cudaEventDisableTiming);

    // fork: GEMM on side stream (compute-bound, hides under L2-bound build)
    cudaEventRecord(evFork, 0);
    cudaStreamWaitEvent(s2, evFork, 0);
    gemm_kernel<<<gemm_blocks, 256, 0, s2>>>(x, W, b, h);
    cudaEventRecord(evGemm, s2);

    // origin stream: zero counters via memset node, then scatter
    cudaMemsetAsync(cnt, 0, (size_t)N_ADJ * N_NODES * sizeof(int), 0);
    scatter_kernel<<<edge_grid, 256>>>(adj_rows, adj_cols, adj_vals,
                                       idxes_seq, idxes_res);

    // join: SpMM chain needs both h and the buckets
    cudaStreamWaitEvent(0, evGemm, 0);
    spmm_k1<<<row_blocks, 256>>>(idxes_seq);
    spmm_k2<<<row_blocks, 256>>>(idxes_seq, idxes_res);
    spmm_k3a<<<row_blocks, 256>>>(idxes_res);
    spmm_k3b_ln<<<row_blocks, 256>>>(idxes_seq, gamma, beta, out);
}

// round 15
// speedup vs baseline: 1.0269x; 1.0151x over previous
#include <cuda_runtime.h>
#include <cuda_fp16.h>
#include <math.h>

#define N_NODES 50000
#define NNZ     800000
#define N_ADJ   6
#define K_IN    256
#define N_HID   128
#define LN_EPS  1e-5f
#define CAP     64          // bucket capacity (Poisson(16): P(>40)~2e-7)

// ---- scratch (no allocation allowed -> __device__ globals) ----
__device__ __half   g_h [N_NODES * N_HID];
__device__ __half   g_s1[N_NODES * N_HID];
__device__ __half   g_s2[N_NODES * N_HID];
__device__ int      g_cnt [N_ADJ * N_NODES];
__device__ unsigned g_pedge[(size_t)N_ADJ * N_NODES * CAP]; // {col lo16, half(val) hi16}

// ---- helpers ----
__device__ __forceinline__ uint2 f4_to_h4(float4 a)
{
    __half2 lo = __floats2half2_rn(a.x, a.y);
    __half2 hi = __floats2half2_rn(a.z, a.w);
    uint2 u;
    u.x = *reinterpret_cast<unsigned int*>(&lo);
    u.y = *reinterpret_cast<unsigned int*>(&hi);
    return u;
}

// acc[8] += v * (8 halfs packed in uint4)
__device__ __forceinline__ void fma_h8(float* acc, float v, uint4 u)
{
    unsigned p[4] = {u.x, u.y, u.z, u.w};
#pragma unroll
    for (int q = 0; q < 4; q++) {
        __half2 hh = *reinterpret_cast<__half2*>(&p[q]);
        float2 f = __half22float2(hh);
        acc[q * 2 + 0] = fmaf(v, f.x, acc[q * 2 + 0]);
        acc[q * 2 + 1] = fmaf(v, f.y, acc[q * 2 + 1]);
    }
}

__device__ __forceinline__ float hbits_to_f(unsigned hi16)
{
    return __half2float(__ushort_as_half((unsigned short)hi16));
}

// inline "is adjacency a used?" check
__device__ __forceinline__ bool adj_used(
    int a, const int* __restrict__ seq, const int* __restrict__ res)
{
    return a == seq[0] || a == seq[1] || a == seq[2] ||
           a == res[0] || a == res[1] || a == res[2];
}

// ============================================================================
// GEMM (R9 fp32 version): h = x @ W + b   (fp32 math, fp16 store)
// ============================================================================
#define GR 64
#define KC 32

__global__ __launch_bounds__(256) void gemm_kernel(
    const float* __restrict__ x, const float* __restrict__ W,
    const float* __restrict__ b, __half* __restrict__ out)
{
    __shared__ __align__(16) float xs[KC][GR];
    __shared__ __align__(16) float ws[KC][N_HID];

    const int tid = threadIdx.x;
    const int tx = tid & 31;
    const int ty = tid >> 5;
    const int row0 = blockIdx.x * GR;

    float acc[8][4];
#pragma unroll
    for (int i = 0; i < 8; i++)
#pragma unroll
        for (int j = 0; j < 4; j++) acc[i][j] = 0.f;

    for (int kc = 0; kc < K_IN; kc += KC) {
#pragma unroll
        for (int t = 0; t < 2; t++) {
            int idx = tid + t * 256;
            int r   = idx >> 3;
            int kq  = idx & 7;
            float4 v = make_float4(0.f, 0.f, 0.f, 0.f);
            int grow = row0 + r;
            if (grow < N_NODES)
                v = *(const float4*)(x + (size_t)grow * K_IN + kc + kq * 4);
            xs[kq * 4 + 0][r] = v.x;
            xs[kq * 4 + 1][r] = v.y;
            xs[kq * 4 + 2][r] = v.z;
            xs[kq * 4 + 3][r] = v.w;
        }
#pragma unroll
        for (int t = 0; t < 4; t++) {
            int idx = tid + t * 256;
            int kk  = idx >> 5;
            int c4  = idx & 31;
            *(float4*)&ws[kk][c4 * 4] =
                *(const float4*)(W + (size_t)(kc + kk) * N_HID + c4 * 4);
        }
        __syncthreads();

#pragma unroll
        for (int k = 0; k < KC; k++) {
            float4 xa = *(const float4*)&xs[k][ty * 8];
            float4 xb = *(const float4*)&xs[k][ty * 8 + 4];
            float4 wv = *(const float4*)&ws[k][tx * 4];
            float xr[8] = {xa.x, xa.y, xa.z, xa.w, xb.x, xb.y, xb.z, xb.w};
            float wr[4] = {wv.x, wv.y, wv.z, wv.w};
#pragma unroll
            for (int i = 0; i < 8; i++)
#pragma unroll
                for (int j = 0; j < 4; j++) acc[i][j] += xr[i] * wr[j];
        }
        __syncthreads();
    }

    float4 bv = *(const float4*)(b + tx * 4);
#pragma unroll
    for (int i = 0; i < 8; i++) {
        int grow = row0 + ty * 8 + i;
        if (grow < N_NODES) {
            float4 o;
            o.x = acc[i][0] + bv.x;
            o.y = acc[i][1] + bv.y;
            o.z = acc[i][2] + bv.z;
            o.w = acc[i][3] + bv.w;
            ((uint2*)out)[(size_t)grow * 32 + tx] = f4_to_h4(o);
        }
    }
}

// ============================================================================
// bucket scatter: 4B packed records, atomic cursor (counters zeroed by memset)
// ============================================================================
__global__ __launch_bounds__(256) void scatter_kernel(
    const int* __restrict__ rows, const int* __restrict__ cols,
    const float* __restrict__ vals,
    const int* __restrict__ seq, const int* __restrict__ res)
{
    int a = blockIdx.y;
    if (!adj_used(a, seq, res)) return;
    int e = blockIdx.x * 256 + threadIdx.x;
    if (e >= NNZ) return;
    size_t idx = (size_t)a * NNZ + e;
    int r = rows[idx];
    int p = atomicAdd(&g_cnt[a * N_NODES + r], 1);
    if (p < CAP) {
        unsigned hv = __half_as_ushort(__float2half_rn(vals[idx]));
        unsigned pk = (unsigned)cols[idx] | (hv << 16);   // col < 65536
        g_pedge[((size_t)a * N_NODES + r) * CAP + p] = pk;
    }
}

// ============================================================================
// Gather SpMM (R9 form): HALF-WARP per row; sub-lane s owns cols [8s,8s+8).
// Segment-masked shuffles; padded slots hold packed 0 -> fma no-op.
// ============================================================================
__device__ __forceinline__ void accum_row8(
    float* acc, int a, int row, const uint4* __restrict__ src,
    int sub, unsigned seg)
{
    int n = g_cnt[a * N_NODES + row];
    n = n < CAP ? n : CAP;
    const unsigned* ep = g_pedge + ((size_t)a * N_NODES + row) * CAP;

    unsigned m[4];
#pragma unroll
    for (int j = 0; j < 4; j++)
        m[j] = (sub + 16 * j < n) ? __ldg(ep + sub + 16 * j) : 0u;

    int n8 = (n + 7) & ~7;
    for (int e = 0; e < n8; e += 8) {
        unsigned mm = (e & 16) ? ((e & 32) ? m[3] : m[1])
                               : ((e & 32) ? m[2] : m[0]);
        int sl = e & 15;
        unsigned w[8];
#pragma unroll
        for (int j = 0; j < 8; j++)
            w[j] = __shfl_sync(seg, mm, sl + j, 16);

        uint4 xv[8];
#pragma unroll
        for (int j = 0; j < 8; j++)
            xv[j] = __ldg(src + (size_t)(w[j] & 0xFFFFu) * 16 + sub);
#pragma unroll
        for (int j = 0; j < 8; j++)
            fma_h8(acc, hbits_to_f(w[j] >> 16), xv[j]);
    }
}

__device__ __forceinline__ uint4 f8_to_h8(const float* a)
{
    __half2 h0 = __floats2half2_rn(a[0], a[1]);
    __half2 h1 = __floats2half2_rn(a[2], a[3]);
    __half2 h2 = __floats2half2_rn(a[4], a[5]);
    __half2 h3 = __floats2half2_rn(a[6], a[7]);
    uint4 u;
    u.x = *reinterpret_cast<unsigned*>(&h0);
    u.y = *reinterpret_cast<unsigned*>(&h1);
    u.z = *reinterpret_cast<unsigned*>(&h2);
    u.w = *reinterpret_cast<unsigned*>(&h3);
    return u;
}

// s1 = A[seq0] @ h        (16 rows per 256-thread block; 50000/16 = 3125 exact)
__global__ __launch_bounds__(256) void spmm_k1(const int* __restrict__ idx_seq)
{
    int lane = threadIdx.x & 31;
    int sub  = lane & 15;
    unsigned seg = 0xFFFFu << ((lane >> 4) * 16);
    int row  = blockIdx.x * 16 + (threadIdx.x >> 5) * 2 + (lane >> 4);
    float acc[8] = {0.f, 0.f, 0.f, 0.f, 0.f, 0.f, 0.f, 0.f};
    accum_row8(acc, idx_seq[0], row, (const uint4*)g_h, sub, seg);
    ((uint4*)g_s1)[(size_t)row * 16 + sub] = f8_to_h8(acc);
}

// s2 = A[seq1] @ s1 + A[res0] @ h
__global__ __launch_bounds__(256) void spmm_k2(
    const int* __restrict__ idx_seq, const int* __restrict__ idx_res)
{
    int lane = threadIdx.x & 31;
    int sub  = lane & 15;
    unsigned seg = 0xFFFFu << ((lane >> 4) * 16);
    int row  = blockIdx.x * 16 + (threadIdx.x >> 5) * 2 + (lane >> 4);
    float acc[8] = {0.f, 0.f, 0.f, 0.f, 0.f, 0.f, 0.f, 0.f};
    accum_row8(acc, idx_seq[1], row, (const uint4*)g_s1, sub, seg);
    accum_row8(acc, idx_res[0], row, (const uint4*)g_h,  sub, seg);
    ((uint4*)g_s2)[(size_t)row * 16 + sub] = f8_to_h8(acc);
}

__device__ __forceinline__ float gelu_exact(float x)
{
    return 0.5f * x * (1.f + erff(x * 0.70710678118654752f));
}

// out = LN+GELU( A[seq2] @ s2 + A[res1] @ h + A[res2] @ s1 )   (fp32 out)
__global__ __launch_bounds__(256) void spmm_k3_ln(
    const int* __restrict__ idx_seq, const int* __restrict__ idx_res,
    const float* __restrict__ gamma, const float* __restrict__ beta,
    float* __restrict__ out)
{
    int lane = threadIdx.x & 31;
    int sub  = lane & 15;
    unsigned seg = 0xFFFFu << ((lane >> 4) * 16);
    int row  = blockIdx.x * 16 + (threadIdx.x >> 5) * 2 + (lane >> 4);
    float acc[8] = {0.f, 0.f, 0.f, 0.f, 0.f, 0.f, 0.f, 0.f};
    accum_row8(acc, idx_seq[2], row, (const uint4*)g_s2, sub, seg);
    accum_row8(acc, idx_res[1], row, (const uint4*)g_h,  sub, seg);
    accum_row8(acc, idx_res[2], row, (const uint4*)g_s1, sub, seg);

    float s = 0.f, sq = 0.f;
#pragma unroll
    for (int j = 0; j < 8; j++) { s += acc[j]; sq += acc[j] * acc[j]; }
#pragma unroll
    for (int o = 8; o > 0; o >>= 1) {
        s  += __shfl_xor_sync(seg, s,  o, 16);
        sq += __shfl_xor_sync(seg, sq, o, 16);
    }
    float mu   = s * (1.f / 128.f);
    float var  = sq * (1.f / 128.f) - mu * mu;
    float rstd = rsqrtf(var + LN_EPS);

    float4 g0  = *(const float4*)(gamma + sub * 8);
    float4 g1  = *(const float4*)(gamma + sub * 8 + 4);
    float4 b0  = *(const float4*)(beta  + sub * 8);
    float4 b1  = *(const float4*)(beta  + sub * 8 + 4);
    float gg[8] = {g0.x, g0.y, g0.z, g0.w, g1.x, g1.y, g1.z, g1.w};
    float bb[8] = {b0.x, b0.y, b0.z, b0.w, b1.x, b1.y, b1.z, b1.w};

    float o8[8];
#pragma unroll
    for (int j = 0; j < 8; j++)
        o8[j] = gelu_exact((acc[j] - mu) * rstd * gg[j] + bb[j]);

    float4* op = (float4*)(out + (size_t)row * N_HID + sub * 8);
    op[0] = make_float4(o8[0], o8[1], o8[2], o8[3]);
    op[1] = make_float4(o8[4], o8[5], o8[6], o8[7]);
}

// ============================================================================
// launch — forked capture: fp32 GEMM (compute-bound) overlaps memset+scatter
// (L2-bound); SpMM chain joins both.
// ============================================================================
extern "C" void kernel_launch(void* const* d_in, const int* in_sizes, int n_in,
                              void* d_out, int out_size)
{
    const float* x         = (const float*)d_in[0];
    const int*   adj_rows  = (const int*)  d_in[1];
    const int*   adj_cols  = (const int*)  d_in[2];
    const float* adj_vals  = (const float*)d_in[3];
    const int*   idxes_seq = (const int*)  d_in[4];
    const int*   idxes_res = (const int*)  d_in[5];
    const float* W         = (const float*)d_in[6];
    const float* b         = (const float*)d_in[7];
    const float* gamma     = (const float*)d_in[8];
    const float* beta      = (const float*)d_in[9];
    float*       out       = (float*)d_out;

    __half* h;
    int*    cnt;
    cudaGetSymbolAddress((void**)&h,   g_h);
    cudaGetSymbolAddress((void**)&cnt, g_cnt);

    const int  gemm_blocks = (N_NODES + GR - 1) / GR;          // 782
    const dim3 edge_grid((NNZ + 255) / 256, N_ADJ);
    const int  row_blocks  = N_NODES / 16;                     // 3125 exact

    cudaStream_t s2;
    cudaStreamCreateWithFlags(&s2, cudaStreamNonBlocking);
    cudaEvent_t evFork, evGemm;
    cudaEventCreateWithFlags(&evFork, cudaEventDisableTiming);
    cudaEventCreateWithFlags(&evGemm, cudaEventDisableTiming);

    // fork: GEMM on side stream (compute-bound, hides under L2-bound build)
    cudaEventRecord(evFork, 0);
    cudaStreamWaitEvent(s2, evFork, 0);
    gemm_kernel<<<gemm_blocks, 256, 0, s2>>>(x, W, b, h);
    cudaEventRecord(evGemm, s2);

    // origin stream: zero counters via memset node, then scatter
    cudaMemsetAsync(cnt, 0, (size_t)N_ADJ * N_NODES * sizeof(int), 0);
    scatter_kernel<<<edge_grid, 256>>>(adj_rows, adj_cols, adj_vals,
                                       idxes_seq, idxes_res);

    // join: SpMM chain needs both h and the buckets
    cudaStreamWaitEvent(0, evGemm, 0);
    spmm_k1<<<row_blocks, 256>>>(idxes_seq);
    spmm_k2<<<row_blocks, 256>>>(idxes_seq, idxes_res);
    spmm_k3_ln<<<row_blocks, 256>>>(idxes_seq, idxes_res, gamma, beta, out);
}

// round 16
// speedup vs baseline: 1.0292x; 1.0023x over previous
#include <cuda_runtime.h>
#include <cuda_fp16.h>
#include <math.h>

#define N_NODES 50000
#define NNZ     800000
#define N_ADJ   6
#define K_IN    256
#define N_HID   128
#define LN_EPS  1e-5f
#define CAP     48          // bucket capacity (Poisson(16): P(>48)~1e-11)

// ---- scratch (no allocation allowed -> __device__ globals) ----
__device__ __half   g_h [N_NODES * N_HID];
__device__ __half   g_s1[N_NODES * N_HID];
__device__ __half   g_s2[N_NODES * N_HID];
__device__ int      g_cnt [N_ADJ * N_NODES];
__device__ unsigned g_pedge[(size_t)N_ADJ * N_NODES * CAP]; // {col lo16, half(val) hi16}

// ---- helpers ----
__device__ __forceinline__ uint2 f4_to_h4(float4 a)
{
    __half2 lo = __floats2half2_rn(a.x, a.y);
    __half2 hi = __floats2half2_rn(a.z, a.w);
    uint2 u;
    u.x = *reinterpret_cast<unsigned int*>(&lo);
    u.y = *reinterpret_cast<unsigned int*>(&hi);
    return u;
}

// acc[8] += v * (8 halfs packed in uint4)
__device__ __forceinline__ void fma_h8(float* acc, float v, uint4 u)
{
    unsigned p[4] = {u.x, u.y, u.z, u.w};
#pragma unroll
    for (int q = 0; q < 4; q++) {
        __half2 hh = *reinterpret_cast<__half2*>(&p[q]);
        float2 f = __half22float2(hh);
        acc[q * 2 + 0] = fmaf(v, f.x, acc[q * 2 + 0]);
        acc[q * 2 + 1] = fmaf(v, f.y, acc[q * 2 + 1]);
    }
}

__device__ __forceinline__ float hbits_to_f(unsigned hi16)
{
    return __half2float(__ushort_as_half((unsigned short)hi16));
}

// inline "is adjacency a used?" check
__device__ __forceinline__ bool adj_used(
    int a, const int* __restrict__ seq, const int* __restrict__ res)
{
    return a == seq[0] || a == seq[1] || a == seq[2] ||
           a == res[0] || a == res[1] || a == res[2];
}

// ============================================================================
// GEMM: h = x @ W + b   (fp32 math, fp16 store)
// ============================================================================
#define GR 64
#define KC 32

__global__ __launch_bounds__(256) void gemm_kernel(
    const float* __restrict__ x, const float* __restrict__ W,
    const float* __restrict__ b, __half* __restrict__ out)
{
    __shared__ __align__(16) float xs[KC][GR];
    __shared__ __align__(16) float ws[KC][N_HID];

    const int tid = threadIdx.x;
    const int tx = tid & 31;
    const int ty = tid >> 5;
    const int row0 = blockIdx.x * GR;

    float acc[8][4];
#pragma unroll
    for (int i = 0; i < 8; i++)
#pragma unroll
        for (int j = 0; j < 4; j++) acc[i][j] = 0.f;

    for (int kc = 0; kc < K_IN; kc += KC) {
#pragma unroll
        for (int t = 0; t < 2; t++) {
            int idx = tid + t * 256;
            int r   = idx >> 3;
            int kq  = idx & 7;
            float4 v = make_float4(0.f, 0.f, 0.f, 0.f);
            int grow = row0 + r;
            if (grow < N_NODES)
                v = *(const float4*)(x + (size_t)grow * K_IN + kc + kq * 4);
            xs[kq * 4 + 0][r] = v.x;
            xs[kq * 4 + 1][r] = v.y;
            xs[kq * 4 + 2][r] = v.z;
            xs[kq * 4 + 3][r] = v.w;
        }
#pragma unroll
        for (int t = 0; t < 4; t++) {
            int idx = tid + t * 256;
            int kk  = idx >> 5;
            int c4  = idx & 31;
            *(float4*)&ws[kk][c4 * 4] =
                *(const float4*)(W + (size_t)(kc + kk) * N_HID + c4 * 4);
        }
        __syncthreads();

#pragma unroll
        for (int k = 0; k < KC; k++) {
            float4 xa = *(const float4*)&xs[k][ty * 8];
            float4 xb = *(const float4*)&xs[k][ty * 8 + 4];
            float4 wv = *(const float4*)&ws[k][tx * 4];
            float xr[8] = {xa.x, xa.y, xa.z, xa.w, xb.x, xb.y, xb.z, xb.w};
            float wr[4] = {wv.x, wv.y, wv.z, wv.w};
#pragma unroll
            for (int i = 0; i < 8; i++)
#pragma unroll
                for (int j = 0; j < 4; j++) acc[i][j] += xr[i] * wr[j];
        }
        __syncthreads();
    }

    float4 bv = *(const float4*)(b + tx * 4);
#pragma unroll
    for (int i = 0; i < 8; i++) {
        int grow = row0 + ty * 8 + i;
        if (grow < N_NODES) {
            float4 o;
            o.x = acc[i][0] + bv.x;
            o.y = acc[i][1] + bv.y;
            o.z = acc[i][2] + bv.z;
            o.w = acc[i][3] + bv.w;
            ((uint2*)out)[(size_t)grow * 32 + tx] = f4_to_h4(o);
        }
    }
}

// ============================================================================
// bucket scatter: 4B packed records, atomic cursor (counters zeroed by memset)
// ============================================================================
__global__ __launch_bounds__(256) void scatter_kernel(
    const int* __restrict__ rows, const int* __restrict__ cols,
    const float* __restrict__ vals,
    const int* __restrict__ seq, const int* __restrict__ res)
{
    int a = blockIdx.y;
    if (!adj_used(a, seq, res)) return;
    int e = blockIdx.x * 256 + threadIdx.x;
    if (e >= NNZ) return;
    size_t idx = (size_t)a * NNZ + e;
    int r = rows[idx];
    int p = atomicAdd(&g_cnt[a * N_NODES + r], 1);
    if (p < CAP) {
        unsigned hv = __half_as_ushort(__float2half_rn(vals[idx]));
        unsigned pk = (unsigned)cols[idx] | (hv << 16);   // col < 65536
        g_pedge[((size_t)a * N_NODES + r) * CAP + p] = pk;
    }
}

// ============================================================================
// Gather SpMM: HALF-WARP per row; sub-lane s owns cols [8s,8s+8) (uint4 fp16).
// Segment-masked shuffles; padded slots hold packed 0 -> fma no-op.
// Edge words loaded with __ldcs (streamed once; keep L2 for reused states).
// ============================================================================
__device__ __forceinline__ void accum_row8(
    float* acc, int a, int row, const uint4* __restrict__ src,
    int sub, unsigned seg)
{
    int n = g_cnt[a * N_NODES + row];
    n = n < CAP ? n : CAP;
    const unsigned* ep = g_pedge + ((size_t)a * N_NODES + row) * CAP;

    unsigned m[3];
#pragma unroll
    for (int j = 0; j < 3; j++)
        m[j] = (sub + 16 * j < n) ? __ldcs(ep + sub + 16 * j) : 0u;

    int n8 = (n + 7) & ~7;
    for (int e = 0; e < n8; e += 8) {
        unsigned mm = (e & 32) ? m[2] : ((e & 16) ? m[1] : m[0]);
        int sl = e & 15;
        unsigned w[8];
#pragma unroll
        for (int j = 0; j < 8; j++)
            w[j] = __shfl_sync(seg, mm, sl + j, 16);

        uint4 xv[8];
#pragma unroll
        for (int j = 0; j < 8; j++)
            xv[j] = __ldg(src + (size_t)(w[j] & 0xFFFFu) * 16 + sub);
#pragma unroll
        for (int j = 0; j < 8; j++)
            fma_h8(acc, hbits_to_f(w[j] >> 16), xv[j]);
    }
}

__device__ __forceinline__ uint4 f8_to_h8(const float* a)
{
    __half2 h0 = __floats2half2_rn(a[0], a[1]);
    __half2 h1 = __floats2half2_rn(a[2], a[3]);
    __half2 h2 = __floats2half2_rn(a[4], a[5]);
    __half2 h3 = __floats2half2_rn(a[6], a[7]);
    uint4 u;
    u.x = *reinterpret_cast<unsigned*>(&h0);
    u.y = *reinterpret_cast<unsigned*>(&h1);
    u.z = *reinterpret_cast<unsigned*>(&h2);
    u.w = *reinterpret_cast<unsigned*>(&h3);
    return u;
}

// s1 = A[seq0] @ h        (16 rows per 256-thread block; 50000/16 = 3125 exact)
__global__ __launch_bounds__(256) void spmm_k1(const int* __restrict__ idx_seq)
{
    int lane = threadIdx.x & 31;
    int sub  = lane & 15;
    unsigned seg = 0xFFFFu << ((lane >> 4) * 16);
    int row  = blockIdx.x * 16 + (threadIdx.x >> 5) * 2 + (lane >> 4);
    float acc[8] = {0.f, 0.f, 0.f, 0.f, 0.f, 0.f, 0.f, 0.f};
    accum_row8(acc, idx_seq[0], row, (const uint4*)g_h, sub, seg);
    ((uint4*)g_s1)[(size_t)row * 16 + sub] = f8_to_h8(acc);
}

// s2 = A[seq1] @ s1 + A[res0] @ h
__global__ __launch_bounds__(256) void spmm_k2(
    const int* __restrict__ idx_seq, const int* __restrict__ idx_res)
{
    int lane = threadIdx.x & 31;
    int sub  = lane & 15;
    unsigned seg = 0xFFFFu << ((lane >> 4) * 16);
    int row  = blockIdx.x * 16 + (threadIdx.x >> 5) * 2 + (lane >> 4);
    float acc[8] = {0.f, 0.f, 0.f, 0.f, 0.f, 0.f, 0.f, 0.f};
    accum_row8(acc, idx_seq[1], row, (const uint4*)g_s1, sub, seg);
    accum_row8(acc, idx_res[0], row, (const uint4*)g_h,  sub, seg);
    ((uint4*)g_s2)[(size_t)row * 16 + sub] = f8_to_h8(acc);
}

__device__ __forceinline__ float gelu_exact(float x)
{
    return 0.5f * x * (1.f + erff(x * 0.70710678118654752f));
}

// out = LN+GELU( A[seq2] @ s2 + A[res1] @ h + A[res2] @ s1 )   (fp32 out)
__global__ __launch_bounds__(256) void spmm_k3_ln(
    const int* __restrict__ idx_seq, const int* __restrict__ idx_res,
    const float* __restrict__ gamma, const float* __restrict__ beta,
    float* __restrict__ out)
{
    int lane = threadIdx.x & 31;
    int sub  = lane & 15;
    unsigned seg = 0xFFFFu << ((lane >> 4) * 16);
    int row  = blockIdx.x * 16 + (threadIdx.x >> 5) * 2 + (lane >> 4);
    float acc[8] = {0.f, 0.f, 0.f, 0.f, 0.f, 0.f, 0.f, 0.f};
    accum_row8(acc, idx_seq[2], row, (const uint4*)g_s2, sub, seg);
    accum_row8(acc, idx_res[1], row, (const uint4*)g_h,  sub, seg);
    accum_row8(acc, idx_res[2], row, (const uint4*)g_s1, sub, seg);

    float s = 0.f, sq = 0.f;
#pragma unroll
    for (int j = 0; j < 8; j++) { s += acc[j]; sq += acc[j] * acc[j]; }
#pragma unroll
    for (int o = 8; o > 0; o >>= 1) {
        s  += __shfl_xor_sync(seg, s,  o, 16);
        sq += __shfl_xor_sync(seg, sq, o, 16);
    }
    float mu   = s * (1.f / 128.f);
    float var  = sq * (1.f / 128.f) - mu * mu;
    float rstd = rsqrtf(var + LN_EPS);

    float4 g0  = *(const float4*)(gamma + sub * 8);
    float4 g1  = *(const float4*)(gamma + sub * 8 + 4);
    float4 b0  = *(const float4*)(beta  + sub * 8);
    float4 b1  = *(const float4*)(beta  + sub * 8 + 4);
    float gg[8] = {g0.x, g0.y, g0.z, g0.w, g1.x, g1.y, g1.z, g1.w};
    float bb[8] = {b0.x, b0.y, b0.z, b0.w, b1.x, b1.y, b1.z, b1.w};

    float o8[8];
#pragma unroll
    for (int j = 0; j < 8; j++)
        o8[j] = gelu_exact((acc[j] - mu) * rstd * gg[j] + bb[j]);

    float4* op = (float4*)(out + (size_t)row * N_HID + sub * 8);
    op[0] = make_float4(o8[0], o8[1], o8[2], o8[3]);
    op[1] = make_float4(o8[4], o8[5], o8[6], o8[7]);
}

// ============================================================================
// launch — forked capture: fp32 GEMM (compute-bound) overlaps memset+scatter
// (L2-bound); SpMM chain joins both.
// ============================================================================
extern "C" void kernel_launch(void* const* d_in, const int* in_sizes, int n_in,
                              void* d_out, int out_size)
{
    const float* x         = (const float*)d_in[0];
    const int*   adj_rows  = (const int*)  d_in[1];
    const int*   adj_cols  = (const int*)  d_in[2];
    const float* adj_vals  = (const float*)d_in[3];
    const int*   idxes_seq = (const int*)  d_in[4];
    const int*   idxes_res = (const int*)  d_in[5];
    const float* W         = (const float*)d_in[6];
    const float* b         = (const float*)d_in[7];
    const float* gamma     = (const float*)d_in[8];
    const float* beta      = (const float*)d_in[9];
    float*       out       = (float*)d_out;

    __half* h;
    int*    cnt;
    cudaGetSymbolAddress((void**)&h,   g_h);
    cudaGetSymbolAddress((void**)&cnt, g_cnt);

    const int  gemm_blocks = (N_NODES + GR - 1) / GR;          // 782
    const dim3 edge_grid((NNZ + 255) / 256, N_ADJ);
    const int  row_blocks  = N_NODES / 16;                     // 3125 exact

    cudaStream_t s2;
    cudaStreamCreateWithFlags(&s2, cudaStreamNonBlocking);
    cudaEvent_t evFork, evGemm;
    cudaEventCreateWithFlags(&evFork, cudaEventDisableTiming);
    cudaEventCreateWithFlags(&evGemm, cudaEventDisableTiming);

    // fork: GEMM on side stream (compute-bound, hides under L2-bound build)
    cudaEventRecord(evFork, 0);
    cudaStreamWaitEvent(s2, evFork, 0);
    gemm_kernel<<<gemm_blocks, 256, 0, s2>>>(x, W, b, h);
    cudaEventRecord(evGemm, s2);

    // origin stream: zero counters via memset node, then scatter
    cudaMemsetAsync(cnt, 0, (size_t)N_ADJ * N_NODES * sizeof(int), 0);
    scatter_kernel<<<edge_grid, 256>>>(adj_rows, adj_cols, adj_vals,
                                       idxes_seq, idxes_res);

    // join: SpMM chain needs both h and the buckets
    cudaStreamWaitEvent(0, evGemm, 0);
    spmm_k1<<<row_blocks, 256>>>(idxes_seq);
    spmm_k2<<<row_blocks, 256>>>(idxes_seq, idxes_res);
    spmm_k3_ln<<<row_blocks, 256>>>(idxes_seq, idxes_res, gamma, beta, out);
}